// round 2
// baseline (speedup 1.0000x reference)
#include <cuda_runtime.h>
#include <math.h>

// Problem shape (fixed by the dataset)
#define NE_MAX 100000
#define NR_MAX 1000
#define E_MAX  500000

// ---------------- scratch (device globals: no allocation allowed) -------------
__device__ float g_HT[NE_MAX * 256];   // [n][0:128]=Ent@W_h, [n][128:256]=Ent@W_t
__device__ float g_RE[NR_MAX * 256];   // [r][0:128]=Rel@W_r
__device__ float g_sh[NE_MAX];
__device__ float g_st[NE_MAX];
__device__ float g_sr[NR_MAX];
__device__ int   g_deg[NE_MAX];
__device__ int   g_off[NE_MAX + 1];
__device__ int   g_cur[NE_MAX];
__device__ int   g_edges[E_MAX];

// ---------------- K0: init ----------------------------------------------------
__global__ void k_init(int ne) {
    int i = blockIdx.x * blockDim.x + threadIdx.x;
    if (i < ne) g_deg[i] = 0;
}

// ---------------- K1: GEMM  C[n][256] = A[n][128] @ [W(off0) | W(off1)] -------
// 32 rows/block, 256 threads, per-thread tile 4 rows x 8 cols, k-chunks of 32.
__global__ __launch_bounds__(256) void k_gemm(
    const float* __restrict__ A, int n_rows,
    const float* __restrict__ W, int off0, int off1,
    float* __restrict__ C)
{
    __shared__ float Asm[32][32];
    __shared__ float Wsm[32][256];
    const int t = threadIdx.x;
    const int c = t & 31;        // col group: cols [8c, 8c+8)
    const int r = t >> 5;        // row group: rows [4r, 4r+4)
    const int row0 = blockIdx.x * 32;

    float acc[4][8];
#pragma unroll
    for (int i = 0; i < 4; i++)
#pragma unroll
        for (int j = 0; j < 8; j++) acc[i][j] = 0.f;

    for (int kc = 0; kc < 128; kc += 32) {
        // stage A chunk: rows [row0,row0+32) x k [kc,kc+32)
        {
            int arow = t >> 3;
            int k4 = (t & 7) * 4;
            int gr = row0 + arow;
            float4 v = make_float4(0.f, 0.f, 0.f, 0.f);
            if (gr < n_rows) v = *(const float4*)&A[gr * 128 + kc + k4];
            *(float4*)&Asm[arow][k4] = v;
        }
        // stage W chunk: 32 k-rows x 256 combined cols
#pragma unroll
        for (int i = 0; i < 8; i++) {
            int f  = t + i * 256;        // float4 index in [0,2048)
            int kk = f >> 6;
            int jc = f & 63;
            int j  = jc * 4;
            const float* src = (j < 128)
                ? &W[(off0 + kc + kk) * 128 + j]
                : &W[(off1 + kc + kk) * 128 + (j - 128)];
            *(float4*)&Wsm[kk][j] = *(const float4*)src;
        }
        __syncthreads();
#pragma unroll
        for (int kk = 0; kk < 32; kk++) {
            float4 w0 = *(const float4*)&Wsm[kk][c * 8];
            float4 w1 = *(const float4*)&Wsm[kk][c * 8 + 4];
#pragma unroll
            for (int i = 0; i < 4; i++) {
                float av = Asm[4 * r + i][kk];
                acc[i][0] += av * w0.x; acc[i][1] += av * w0.y;
                acc[i][2] += av * w0.z; acc[i][3] += av * w0.w;
                acc[i][4] += av * w1.x; acc[i][5] += av * w1.y;
                acc[i][6] += av * w1.z; acc[i][7] += av * w1.w;
            }
        }
        __syncthreads();
    }
#pragma unroll
    for (int i = 0; i < 4; i++) {
        int gr = row0 + 4 * r + i;
        if (gr < n_rows) {
            *(float4*)&C[gr * 256 + c * 8]     = make_float4(acc[i][0], acc[i][1], acc[i][2], acc[i][3]);
            *(float4*)&C[gr * 256 + c * 8 + 4] = make_float4(acc[i][4], acc[i][5], acc[i][6], acc[i][7]);
        }
    }
}

// ---------------- K2: per-row dots with attention vector a --------------------
// out0[n] = dot(M[n][0:128], a); if both: out1[n] = dot(M[n][128:256], a)
__global__ void k_dots(const float* __restrict__ M, int n,
                       const float* __restrict__ a,
                       float* __restrict__ out0, float* __restrict__ out1)
{
    int w = (blockIdx.x * blockDim.x + threadIdx.x) >> 5;
    int lane = threadIdx.x & 31;
    if (w >= n) return;
    float4 av = *(const float4*)&a[lane * 4];
    float4 m0 = *(const float4*)&M[w * 256 + lane * 4];
    float s0 = m0.x * av.x + m0.y * av.y + m0.z * av.z + m0.w * av.w;
    float s1 = 0.f;
    if (out1) {
        float4 m1 = *(const float4*)&M[w * 256 + 128 + lane * 4];
        s1 = m1.x * av.x + m1.y * av.y + m1.z * av.z + m1.w * av.w;
    }
#pragma unroll
    for (int d = 16; d; d >>= 1) {
        s0 += __shfl_xor_sync(0xFFFFFFFFu, s0, d);
        s1 += __shfl_xor_sync(0xFFFFFFFFu, s1, d);
    }
    if (lane == 0) {
        out0[w] = s0;
        if (out1) out1[w] = s1;
    }
}

// ---------------- K3: histogram of destination degrees ------------------------
__global__ void k_hist(const int* __restrict__ h_index, int e) {
    int i = blockIdx.x * blockDim.x + threadIdx.x;
    if (i < e) atomicAdd(&g_deg[h_index[i]], 1);
}

// ---------------- K4: single-block exclusive scan (warp-shuffle based) --------
__global__ __launch_bounds__(1024) void k_scan(int n) {
    __shared__ int warp_tot[32];
    __shared__ int sbase;
    const int t = threadIdx.x;
    const int lane = t & 31;
    const int wid = t >> 5;
    if (t == 0) sbase = 0;
    __syncthreads();
    for (int base = 0; base < n; base += 1024) {
        int i = base + t;
        int v = (i < n) ? g_deg[i] : 0;
        // warp inclusive scan
        int s = v;
#pragma unroll
        for (int d = 1; d < 32; d <<= 1) {
            int x = __shfl_up_sync(0xFFFFFFFFu, s, d);
            if (lane >= d) s += x;
        }
        if (lane == 31) warp_tot[wid] = s;
        __syncthreads();
        if (wid == 0) {
            int wv = warp_tot[lane];
            int ws = wv;
#pragma unroll
            for (int d = 1; d < 32; d <<= 1) {
                int x = __shfl_up_sync(0xFFFFFFFFu, ws, d);
                if (lane >= d) ws += x;
            }
            warp_tot[lane] = ws - wv;  // exclusive
        }
        __syncthreads();
        int excl = sbase + warp_tot[wid] + (s - v);
        if (i < n) { g_off[i] = excl; g_cur[i] = excl; }
        __syncthreads();
        if (t == 1023) sbase = excl + v;
        __syncthreads();
    }
    if (t == 0) g_off[n] = sbase;
}

// ---------------- K5: scatter edge ids into CSR -------------------------------
__global__ void k_scatter(const int* __restrict__ h_index, int e) {
    int i = blockIdx.x * blockDim.x + threadIdx.x;
    if (i < e) {
        int p = atomicAdd(&g_cur[h_index[i]], 1);
        g_edges[p] = i;
    }
}

// ---------------- K6: fused segment softmax + weighted reduce + bias + relu ---
// One warp per destination entity.
// out[n][:] = relu(HE[n] + (Σ w_e (RE[r_e]+TE[t_e]))/Σ w_e + bias)
__global__ void k_fused(const int* __restrict__ r_index, const int* __restrict__ t_index,
                        const float* __restrict__ a_b, const float* __restrict__ bias,
                        float* __restrict__ out, int ne)
{
    int w = (blockIdx.x * blockDim.x + threadIdx.x) >> 5;
    int lane = threadIdx.x & 31;
    if (w >= ne) return;
    int o0 = g_off[w];
    int deg = g_off[w + 1] - o0;
    float4 b4 = *(const float4*)&bias[lane * 4];
    float4 res;
    if (deg == 0) {
        // empty segment: reference reduces to relu(bias)
        res.x = fmaxf(b4.x, 0.f); res.y = fmaxf(b4.y, 0.f);
        res.z = fmaxf(b4.z, 0.f); res.w = fmaxf(b4.w, 0.f);
    } else {
        float sb = g_sh[w] + a_b[0];
        // pass 1: segment max (lane-strided)
        float lm = -INFINITY;
        for (int i = lane; i < deg; i += 32) {
            int e = g_edges[o0 + i];
            float s = sb + g_sr[r_index[e]] + g_st[t_index[e]];
            s = (s >= 0.f) ? s : 0.2f * s;       // inner leaky
            s = (s >= 0.f) ? s : 0.2f * s;       // outer leaky (match ref exactly)
            lm = fmaxf(lm, s);
        }
#pragma unroll
        for (int d = 16; d; d >>= 1) lm = fmaxf(lm, __shfl_xor_sync(0xFFFFFFFFu, lm, d));
        // pass 2: warp-wide per-edge accumulation (lanes split the 128 dims)
        float denom = 0.f;
        float4 acc = make_float4(0.f, 0.f, 0.f, 0.f);
        for (int i = 0; i < deg; i++) {
            int e = g_edges[o0 + i];
            int rr = r_index[e];
            int tt = t_index[e];
            float s = sb + g_sr[rr] + g_st[tt];
            s = (s >= 0.f) ? s : 0.2f * s;
            s = (s >= 0.f) ? s : 0.2f * s;
            float wg = __expf(s - lm);
            denom += wg;
            float4 fr = *(const float4*)&g_RE[rr * 256 + lane * 4];
            float4 ft = *(const float4*)&g_HT[tt * 256 + 128 + lane * 4];
            acc.x += wg * (fr.x + ft.x);
            acc.y += wg * (fr.y + ft.y);
            acc.z += wg * (fr.z + ft.z);
            acc.w += wg * (fr.w + ft.w);
        }
        float inv = 1.f / denom;
        float4 he = *(const float4*)&g_HT[w * 256 + lane * 4];
        res.x = fmaxf(he.x + acc.x * inv + b4.x, 0.f);
        res.y = fmaxf(he.y + acc.y * inv + b4.y, 0.f);
        res.z = fmaxf(he.z + acc.z * inv + b4.z, 0.f);
        res.w = fmaxf(he.w + acc.w * inv + b4.w, 0.f);
    }
    *(float4*)&out[w * 128 + lane * 4] = res;
}

// ---------------- host ---------------------------------------------------------
extern "C" void kernel_launch(void* const* d_in, const int* in_sizes, int n_in,
                              void* d_out, int out_size)
{
    const int*   h_index = (const int*)d_in[0];
    const int*   r_index = (const int*)d_in[1];
    const int*   t_index = (const int*)d_in[2];
    const float* ent     = (const float*)d_in[3];
    const float* rel     = (const float*)d_in[4];
    const float* W       = (const float*)d_in[5];
    const float* a       = (const float*)d_in[6];
    const float* a_b     = (const float*)d_in[7];
    const float* bias    = (const float*)d_in[8];
    float* out = (float*)d_out;

    const int E  = in_sizes[0];
    const int NE = in_sizes[3] / 128;
    const int NR = in_sizes[4] / 128;

    float* p_HT; cudaGetSymbolAddress((void**)&p_HT, g_HT);
    float* p_RE; cudaGetSymbolAddress((void**)&p_RE, g_RE);
    float* p_sh; cudaGetSymbolAddress((void**)&p_sh, g_sh);
    float* p_st; cudaGetSymbolAddress((void**)&p_st, g_st);
    float* p_sr; cudaGetSymbolAddress((void**)&p_sr, g_sr);

    // init degree histogram
    k_init<<<(NE + 1023) / 1024, 1024>>>(NE);
    // node transforms: HT = Ent @ [W_h | W_t]; RE = Rel @ [W_r | W_r(dup)]
    k_gemm<<<(NE + 31) / 32, 256>>>(ent, NE, W, 0, 256, p_HT);
    k_gemm<<<(NR + 31) / 32, 256>>>(rel, NR, W, 128, 128, p_RE);
    // attention pre-scores per node
    k_dots<<<(NE * 32 + 255) / 256, 256>>>(p_HT, NE, a, p_sh, p_st);
    k_dots<<<(NR * 32 + 255) / 256, 256>>>(p_RE, NR, a, p_sr, (float*)0);
    // CSR build by destination (h_index)
    k_hist<<<(E + 1023) / 1024, 1024>>>(h_index, E);
    k_scan<<<1, 1024>>>(NE);
    k_scatter<<<(E + 1023) / 1024, 1024>>>(h_index, E);
    // fused softmax + message reduce + bias + relu
    k_fused<<<(NE * 32 + 255) / 256, 256>>>(r_index, t_index, a_b, bias, out, NE);
}

// round 3
// speedup vs baseline: 1.5128x; 1.5128x over previous
#include <cuda_runtime.h>
#include <math.h>
#include <stdint.h>

// Problem shape (fixed by the dataset)
#define NE_MAX 100000
#define NR_MAX 1000
#define E_MAX  500000

// ---------------- scratch (device globals: no allocation allowed) -------------
__device__ float g_HT[NE_MAX * 256];   // [n][0:128]=Ent@W_h, [n][128:256]=Ent@W_t
__device__ float g_RE[NR_MAX * 256];   // [r][0:128]=Rel@W_r
__device__ float g_sh[NE_MAX];
__device__ float g_st[NE_MAX];
__device__ float g_sr[NR_MAX];
__device__ int   g_deg[NE_MAX];
__device__ int   g_off[NE_MAX + 1];
__device__ int   g_cur[NE_MAX];
__device__ int   g_edges[E_MAX];

// ---------------- helpers ------------------------------------------------------
__device__ __forceinline__ uint32_t f2tf32(float x) {
    uint32_t r;
    asm("cvt.rna.tf32.f32 %0, %1;" : "=r"(r) : "f"(x));
    return r;
}

__device__ __forceinline__ void mma_tf32(float4& c,
                                         uint32_t a0, uint32_t a1, uint32_t a2, uint32_t a3,
                                         uint32_t b0, uint32_t b1) {
    asm volatile(
        "mma.sync.aligned.m16n8k8.row.col.f32.tf32.tf32.f32 "
        "{%0,%1,%2,%3}, {%4,%5,%6,%7}, {%8,%9}, {%0,%1,%2,%3};\n"
        : "+f"(c.x), "+f"(c.y), "+f"(c.z), "+f"(c.w)
        : "r"(a0), "r"(a1), "r"(a2), "r"(a3), "r"(b0), "r"(b1));
}

// ---------------- K0: init ----------------------------------------------------
__global__ void k_init(int ne) {
    int i = blockIdx.x * blockDim.x + threadIdx.x;
    if (i < ne) g_deg[i] = 0;
}

// ---------------- K1: tensor-core GEMM + fused attention dot -------------------
// C[n][colbase + 0..128) = A[n][0..128) @ W[woff + 0..128)][0..128)   (tf32 MMA)
// dot[n] = C_block[n][:] . a[:]   (fused epilogue)
// grid.x tiles rows by 64; grid.y in {0,1} selects (woff, colbase, dot target).
// block = 128 threads (4 warps); warp w computes rows [16w, 16w+16) x 128 cols.
#define A_PAD 132
#define W_PAD 136
#define GEMM_SMEM_BYTES ((64 * A_PAD + 128 * W_PAD + 128) * 4)

__global__ __launch_bounds__(128) void k_gemm_tc(
    const float* __restrict__ A, int n_rows,
    const float* __restrict__ W, int woff0, int woff1,
    float* __restrict__ C,
    float* __restrict__ dot0, float* __restrict__ dot1,
    const float* __restrict__ a_vec)
{
    extern __shared__ uint32_t smem[];
    uint32_t* As  = smem;                  // [64][A_PAD] tf32 bits
    uint32_t* Ws  = As + 64 * A_PAD;       // [128][W_PAD] tf32 bits
    float*    a_s = (float*)(Ws + 128 * W_PAD);  // [128]

    const int t    = threadIdx.x;
    const int warp = t >> 5;
    const int lane = t & 31;
    const int gid  = lane >> 2;   // group id (row within atom)
    const int tig  = lane & 3;    // thread in group
    const int row0 = blockIdx.x * 64;
    const int yy   = blockIdx.y;
    const int woff = yy == 0 ? woff0 : woff1;
    const int colbase = yy * 128;
    float* dotp = yy == 0 ? dot0 : dot1;

    // stage A tile (64 x 128), zero-fill rows past n_rows
#pragma unroll
    for (int i = 0; i < 16; i++) {
        int idx = t + i * 128;            // float4 index in [0, 2048)
        int r   = idx >> 5;
        int c4  = (idx & 31) * 4;
        float4 v = make_float4(0.f, 0.f, 0.f, 0.f);
        int gr = row0 + r;
        if (gr < n_rows) v = *(const float4*)&A[gr * 128 + c4];
        uint32_t* dst = &As[r * A_PAD + c4];
        dst[0] = f2tf32(v.x); dst[1] = f2tf32(v.y);
        dst[2] = f2tf32(v.z); dst[3] = f2tf32(v.w);
    }
    // stage W tile (128 x 128)
#pragma unroll
    for (int i = 0; i < 32; i++) {
        int idx = t + i * 128;            // float4 index in [0, 4096)
        int r   = idx >> 5;
        int c4  = (idx & 31) * 4;
        float4 v = *(const float4*)&W[(woff + r) * 128 + c4];
        uint32_t* dst = &Ws[r * W_PAD + c4];
        dst[0] = f2tf32(v.x); dst[1] = f2tf32(v.y);
        dst[2] = f2tf32(v.z); dst[3] = f2tf32(v.w);
    }
    if (t < 128) a_s[t] = a_vec[t];
    __syncthreads();

    float4 cacc[16];
#pragma unroll
    for (int j = 0; j < 16; j++) cacc[j] = make_float4(0.f, 0.f, 0.f, 0.f);

    const int ra = 16 * warp + gid;
#pragma unroll
    for (int ks = 0; ks < 16; ks++) {
        const int k0 = ks * 8;
        uint32_t a0 = As[ra * A_PAD + k0 + tig];
        uint32_t a1 = As[(ra + 8) * A_PAD + k0 + tig];
        uint32_t a2 = As[ra * A_PAD + k0 + tig + 4];
        uint32_t a3 = As[(ra + 8) * A_PAD + k0 + tig + 4];
#pragma unroll
        for (int j = 0; j < 16; j++) {
            uint32_t b0 = Ws[(k0 + tig) * W_PAD + j * 8 + gid];
            uint32_t b1 = Ws[(k0 + tig + 4) * W_PAD + j * 8 + gid];
            mma_tf32(cacc[j], a0, a1, a2, a3, b0, b1);
        }
    }

    // epilogue: store C and fused dot with a
    const int rg1 = row0 + 16 * warp + gid;
    const int rg2 = rg1 + 8;
    const bool v1 = rg1 < n_rows;
    const bool v2 = rg2 < n_rows;
    float p1 = 0.f, p2 = 0.f;
#pragma unroll
    for (int j = 0; j < 16; j++) {
        int cl = j * 8 + 2 * tig;
        float ax = a_s[cl], ay = a_s[cl + 1];
        p1 += cacc[j].x * ax + cacc[j].y * ay;
        p2 += cacc[j].z * ax + cacc[j].w * ay;
        if (v1) *(float2*)&C[rg1 * 256 + colbase + cl] = make_float2(cacc[j].x, cacc[j].y);
        if (v2) *(float2*)&C[rg2 * 256 + colbase + cl] = make_float2(cacc[j].z, cacc[j].w);
    }
    // reduce over the 4 lanes of the quad (tig dimension)
    p1 += __shfl_xor_sync(0xFFFFFFFFu, p1, 1);
    p1 += __shfl_xor_sync(0xFFFFFFFFu, p1, 2);
    p2 += __shfl_xor_sync(0xFFFFFFFFu, p2, 1);
    p2 += __shfl_xor_sync(0xFFFFFFFFu, p2, 2);
    if (tig == 0) {
        if (v1) dotp[rg1] = p1;
        if (v2) dotp[rg2] = p2;
    }
}

// ---------------- K3: histogram of destination degrees ------------------------
__global__ void k_hist(const int* __restrict__ h_index, int e) {
    int i = blockIdx.x * blockDim.x + threadIdx.x;
    if (i < e) atomicAdd(&g_deg[h_index[i]], 1);
}

// ---------------- K4: single-block exclusive scan (warp-shuffle based) --------
__global__ __launch_bounds__(1024) void k_scan(int n) {
    __shared__ int warp_tot[32];
    __shared__ int sbase;
    const int t = threadIdx.x;
    const int lane = t & 31;
    const int wid = t >> 5;
    if (t == 0) sbase = 0;
    __syncthreads();
    for (int base = 0; base < n; base += 1024) {
        int i = base + t;
        int v = (i < n) ? g_deg[i] : 0;
        int s = v;
#pragma unroll
        for (int d = 1; d < 32; d <<= 1) {
            int x = __shfl_up_sync(0xFFFFFFFFu, s, d);
            if (lane >= d) s += x;
        }
        if (lane == 31) warp_tot[wid] = s;
        __syncthreads();
        if (wid == 0) {
            int wv = warp_tot[lane];
            int ws = wv;
#pragma unroll
            for (int d = 1; d < 32; d <<= 1) {
                int x = __shfl_up_sync(0xFFFFFFFFu, ws, d);
                if (lane >= d) ws += x;
            }
            warp_tot[lane] = ws - wv;  // exclusive
        }
        __syncthreads();
        int excl = sbase + warp_tot[wid] + (s - v);
        if (i < n) { g_off[i] = excl; g_cur[i] = excl; }
        __syncthreads();
        if (t == 1023) sbase = excl + v;
        __syncthreads();
    }
    if (t == 0) g_off[n] = sbase;
}

// ---------------- K5: scatter edge ids into CSR -------------------------------
__global__ void k_scatter(const int* __restrict__ h_index, int e) {
    int i = blockIdx.x * blockDim.x + threadIdx.x;
    if (i < e) {
        int p = atomicAdd(&g_cur[h_index[i]], 1);
        g_edges[p] = i;
    }
}

// ---------------- K6: fused ONLINE segment softmax + reduce + bias + relu -----
// One warp per destination entity; single pass over edges (online softmax).
__global__ void k_fused(const int* __restrict__ r_index, const int* __restrict__ t_index,
                        const float* __restrict__ a_b, const float* __restrict__ bias,
                        float* __restrict__ out, int ne)
{
    int w = (blockIdx.x * blockDim.x + threadIdx.x) >> 5;
    int lane = threadIdx.x & 31;
    if (w >= ne) return;
    int o0 = g_off[w];
    int deg = g_off[w + 1] - o0;
    float4 b4 = *(const float4*)&bias[lane * 4];
    float4 res;
    if (deg == 0) {
        res.x = fmaxf(b4.x, 0.f); res.y = fmaxf(b4.y, 0.f);
        res.z = fmaxf(b4.z, 0.f); res.w = fmaxf(b4.w, 0.f);
    } else {
        float sb = g_sh[w] + a_b[0];
        float m = -INFINITY;
        float denom = 0.f;
        float4 acc = make_float4(0.f, 0.f, 0.f, 0.f);
        for (int i = 0; i < deg; i++) {
            int e = g_edges[o0 + i];
            int rr = r_index[e];
            int tt = t_index[e];
            float s = sb + g_sr[rr] + g_st[tt];
            s = (s >= 0.f) ? s : 0.2f * s;     // inner leaky
            s = (s >= 0.f) ? s : 0.2f * s;     // outer leaky
            float4 fr = *(const float4*)&g_RE[rr * 256 + lane * 4];
            float4 ft = *(const float4*)&g_HT[tt * 256 + 128 + lane * 4];
            float fx = fr.x + ft.x, fy = fr.y + ft.y;
            float fz = fr.z + ft.z, fw = fr.w + ft.w;
            if (s <= m) {                       // warp-uniform branch
                float wg = __expf(s - m);
                denom += wg;
                acc.x += wg * fx; acc.y += wg * fy;
                acc.z += wg * fz; acc.w += wg * fw;
            } else {
                float c = (m == -INFINITY) ? 0.f : __expf(m - s);
                denom = denom * c + 1.f;
                acc.x = acc.x * c + fx; acc.y = acc.y * c + fy;
                acc.z = acc.z * c + fz; acc.w = acc.w * c + fw;
                m = s;
            }
        }
        float inv = 1.f / denom;
        float4 he = *(const float4*)&g_HT[w * 256 + lane * 4];
        res.x = fmaxf(he.x + acc.x * inv + b4.x, 0.f);
        res.y = fmaxf(he.y + acc.y * inv + b4.y, 0.f);
        res.z = fmaxf(he.z + acc.z * inv + b4.z, 0.f);
        res.w = fmaxf(he.w + acc.w * inv + b4.w, 0.f);
    }
    *(float4*)&out[w * 128 + lane * 4] = res;
}

// ---------------- host ---------------------------------------------------------
extern "C" void kernel_launch(void* const* d_in, const int* in_sizes, int n_in,
                              void* d_out, int out_size)
{
    const int*   h_index = (const int*)d_in[0];
    const int*   r_index = (const int*)d_in[1];
    const int*   t_index = (const int*)d_in[2];
    const float* ent     = (const float*)d_in[3];
    const float* rel     = (const float*)d_in[4];
    const float* W       = (const float*)d_in[5];
    const float* a       = (const float*)d_in[6];
    const float* a_b     = (const float*)d_in[7];
    const float* bias    = (const float*)d_in[8];
    float* out = (float*)d_out;

    const int E  = in_sizes[0];
    const int NE = in_sizes[3] / 128;
    const int NR = in_sizes[4] / 128;

    float* p_HT; cudaGetSymbolAddress((void**)&p_HT, g_HT);
    float* p_RE; cudaGetSymbolAddress((void**)&p_RE, g_RE);
    float* p_sh; cudaGetSymbolAddress((void**)&p_sh, g_sh);
    float* p_st; cudaGetSymbolAddress((void**)&p_st, g_st);
    float* p_sr; cudaGetSymbolAddress((void**)&p_sr, g_sr);

    cudaFuncSetAttribute(k_gemm_tc, cudaFuncAttributeMaxDynamicSharedMemorySize,
                         GEMM_SMEM_BYTES);

    // init degree histogram
    k_init<<<(NE + 1023) / 1024, 1024>>>(NE);
    // HT = Ent @ [W_h | W_t] with fused sh/st dots (tensor cores, tf32)
    {
        dim3 grid((NE + 63) / 64, 2);
        k_gemm_tc<<<grid, 128, GEMM_SMEM_BYTES>>>(ent, NE, W, 0, 256, p_HT, p_sh, p_st, a);
    }
    // RE = Rel @ W_r with fused sr dot
    {
        dim3 grid((NR + 63) / 64, 1);
        k_gemm_tc<<<grid, 128, GEMM_SMEM_BYTES>>>(rel, NR, W, 128, 128, p_RE, p_sr, p_sr, a);
    }
    // CSR build by destination (h_index)
    k_hist<<<(E + 1023) / 1024, 1024>>>(h_index, E);
    k_scan<<<1, 1024>>>(NE);
    k_scatter<<<(E + 1023) / 1024, 1024>>>(h_index, E);
    // fused online softmax + message reduce + bias + relu
    k_fused<<<(NE * 32 + 255) / 256, 256>>>(r_index, t_index, a_b, bias, out, NE);
}

// round 5
// speedup vs baseline: 1.9916x; 1.3165x over previous
#include <cuda_runtime.h>
#include <math.h>
#include <stdint.h>

// Problem shape (fixed by the dataset)
#define NE_MAX 100000
#define NR_MAX 1000
#define E_MAX  500000

// ---------------- scratch (device globals: no allocation allowed) -------------
__device__ float g_HT[NE_MAX * 256];   // [n][0:128]=Ent@W_h, [n][128:256]=Ent@W_t
__device__ float g_RE[NR_MAX * 256];   // [r][0:128]=Rel@W_r
__device__ float g_sh[NE_MAX];
__device__ float g_st[NE_MAX];
__device__ float g_sr[NR_MAX];
__device__ int   g_deg[NE_MAX];
__device__ int   g_off[NE_MAX + 1];
__device__ int   g_cur[NE_MAX];
__device__ int   g_bsum[128];
__device__ int2  g_rt[E_MAX];          // CSR-ordered (r_index, t_index)
__device__ float g_srt[E_MAX];         // CSR-ordered sr[r]+st[t]

// ---------------- helpers ------------------------------------------------------
__device__ __forceinline__ uint32_t f2tf32(float x) {
    uint32_t r;
    asm("cvt.rna.tf32.f32 %0, %1;" : "=r"(r) : "f"(x));
    return r;
}

__device__ __forceinline__ void mma_tf32(float4& c,
                                         uint32_t a0, uint32_t a1, uint32_t a2, uint32_t a3,
                                         uint32_t b0, uint32_t b1) {
    asm volatile(
        "mma.sync.aligned.m16n8k8.row.col.f32.tf32.tf32.f32 "
        "{%0,%1,%2,%3}, {%4,%5,%6,%7}, {%8,%9}, {%0,%1,%2,%3};\n"
        : "+f"(c.x), "+f"(c.y), "+f"(c.z), "+f"(c.w)
        : "r"(a0), "r"(a1), "r"(a2), "r"(a3), "r"(b0), "r"(b1));
}

// ---------------- K0: init ----------------------------------------------------
__global__ void k_init(int ne) {
    int i = blockIdx.x * blockDim.x + threadIdx.x;
    if (i < ne) g_deg[i] = 0;
}

// ---------------- K1: tensor-core GEMM + fused attention dot -------------------
#define A_PAD 132
#define W_PAD 136
#define GEMM_SMEM_BYTES ((64 * A_PAD + 128 * W_PAD + 128) * 4)

__global__ __launch_bounds__(128) void k_gemm_tc(
    const float* __restrict__ A, int n_rows,
    const float* __restrict__ W, int woff0, int woff1,
    float* __restrict__ C,
    float* __restrict__ dot0, float* __restrict__ dot1,
    const float* __restrict__ a_vec)
{
    extern __shared__ uint32_t smem[];
    uint32_t* As  = smem;                  // [64][A_PAD] tf32 bits
    uint32_t* Ws  = As + 64 * A_PAD;       // [128][W_PAD] tf32 bits
    float*    a_s = (float*)(Ws + 128 * W_PAD);  // [128]

    const int t    = threadIdx.x;
    const int warp = t >> 5;
    const int lane = t & 31;
    const int gid  = lane >> 2;   // group id (row within atom)
    const int tig  = lane & 3;    // thread in group
    const int row0 = blockIdx.x * 64;
    const int yy   = blockIdx.y;
    const int woff = yy == 0 ? woff0 : woff1;
    const int colbase = yy * 128;
    float* dotp = yy == 0 ? dot0 : dot1;

    // stage A tile (64 x 128), zero-fill rows past n_rows
#pragma unroll
    for (int i = 0; i < 16; i++) {
        int idx = t + i * 128;
        int r   = idx >> 5;
        int c4  = (idx & 31) * 4;
        float4 v = make_float4(0.f, 0.f, 0.f, 0.f);
        int gr = row0 + r;
        if (gr < n_rows) v = *(const float4*)&A[gr * 128 + c4];
        uint32_t* dst = &As[r * A_PAD + c4];
        dst[0] = f2tf32(v.x); dst[1] = f2tf32(v.y);
        dst[2] = f2tf32(v.z); dst[3] = f2tf32(v.w);
    }
    // stage W tile (128 x 128)
#pragma unroll
    for (int i = 0; i < 32; i++) {
        int idx = t + i * 128;
        int r   = idx >> 5;
        int c4  = (idx & 31) * 4;
        float4 v = *(const float4*)&W[(woff + r) * 128 + c4];
        uint32_t* dst = &Ws[r * W_PAD + c4];
        dst[0] = f2tf32(v.x); dst[1] = f2tf32(v.y);
        dst[2] = f2tf32(v.z); dst[3] = f2tf32(v.w);
    }
    if (t < 128) a_s[t] = a_vec[t];
    __syncthreads();

    float4 cacc[16];
#pragma unroll
    for (int j = 0; j < 16; j++) cacc[j] = make_float4(0.f, 0.f, 0.f, 0.f);

    const int ra = 16 * warp + gid;
#pragma unroll
    for (int ks = 0; ks < 16; ks++) {
        const int k0 = ks * 8;
        uint32_t a0 = As[ra * A_PAD + k0 + tig];
        uint32_t a1 = As[(ra + 8) * A_PAD + k0 + tig];
        uint32_t a2 = As[ra * A_PAD + k0 + tig + 4];
        uint32_t a3 = As[(ra + 8) * A_PAD + k0 + tig + 4];
#pragma unroll
        for (int j = 0; j < 16; j++) {
            uint32_t b0 = Ws[(k0 + tig) * W_PAD + j * 8 + gid];
            uint32_t b1 = Ws[(k0 + tig + 4) * W_PAD + j * 8 + gid];
            mma_tf32(cacc[j], a0, a1, a2, a3, b0, b1);
        }
    }

    // epilogue: store C and fused dot with a
    const int rg1 = row0 + 16 * warp + gid;
    const int rg2 = rg1 + 8;
    const bool v1 = rg1 < n_rows;
    const bool v2 = rg2 < n_rows;
    float p1 = 0.f, p2 = 0.f;
#pragma unroll
    for (int j = 0; j < 16; j++) {
        int cl = j * 8 + 2 * tig;
        float ax = a_s[cl], ay = a_s[cl + 1];
        p1 += cacc[j].x * ax + cacc[j].y * ay;
        p2 += cacc[j].z * ax + cacc[j].w * ay;
        if (v1) *(float2*)&C[rg1 * 256 + colbase + cl] = make_float2(cacc[j].x, cacc[j].y);
        if (v2) *(float2*)&C[rg2 * 256 + colbase + cl] = make_float2(cacc[j].z, cacc[j].w);
    }
    p1 += __shfl_xor_sync(0xFFFFFFFFu, p1, 1);
    p1 += __shfl_xor_sync(0xFFFFFFFFu, p1, 2);
    p2 += __shfl_xor_sync(0xFFFFFFFFu, p2, 1);
    p2 += __shfl_xor_sync(0xFFFFFFFFu, p2, 2);
    if (tig == 0) {
        if (v1) dotp[rg1] = p1;
        if (v2) dotp[rg2] = p2;
    }
}

// ---------------- K3: histogram of destination degrees ------------------------
__global__ void k_hist(const int* __restrict__ h_index, int e) {
    int i = blockIdx.x * blockDim.x + threadIdx.x;
    if (i < e) atomicAdd(&g_deg[h_index[i]], 1);
}

// ---------------- K4a: per-block exclusive scan + block sums -------------------
__global__ __launch_bounds__(1024) void k_scan_blk(int n) {
    __shared__ int warp_tot[32];
    const int t = threadIdx.x;
    const int lane = t & 31;
    const int wid = t >> 5;
    int i = blockIdx.x * 1024 + t;
    int v = (i < n) ? g_deg[i] : 0;
    int s = v;
#pragma unroll
    for (int d = 1; d < 32; d <<= 1) {
        int x = __shfl_up_sync(0xFFFFFFFFu, s, d);
        if (lane >= d) s += x;
    }
    if (lane == 31) warp_tot[wid] = s;
    __syncthreads();
    if (wid == 0) {
        int wv = warp_tot[lane];
        int ws = wv;
#pragma unroll
        for (int d = 1; d < 32; d <<= 1) {
            int x = __shfl_up_sync(0xFFFFFFFFu, ws, d);
            if (lane >= d) ws += x;
        }
        warp_tot[lane] = ws - wv;
    }
    __syncthreads();
    int excl = warp_tot[wid] + s - v;
    if (i < n) g_off[i] = excl;            // block-local exclusive
    if (t == 1023) g_bsum[blockIdx.x] = excl + v;
}

// ---------------- K4b: top-level scan of block sums (nb <= 128) ---------------
__global__ __launch_bounds__(128) void k_scan_top(int nb, int etot, int n) {
    __shared__ int wt[4];
    const int t = threadIdx.x;
    const int lane = t & 31;
    const int wid = t >> 5;
    int v = (t < nb) ? g_bsum[t] : 0;
    int s = v;
#pragma unroll
    for (int d = 1; d < 32; d <<= 1) {
        int x = __shfl_up_sync(0xFFFFFFFFu, s, d);
        if (lane >= d) s += x;
    }
    if (lane == 31) wt[wid] = s;
    __syncthreads();
    int off = 0;
#pragma unroll
    for (int k = 0; k < 4; k++) if (k < wid) off += wt[k];
    g_bsum[t] = off + s - v;               // exclusive
    if (t == 0) g_off[n] = etot;
}

// ---------------- K4c: add block offsets, init cursors ------------------------
__global__ __launch_bounds__(1024) void k_scan_add(int n) {
    int i = blockIdx.x * 1024 + threadIdx.x;
    if (i < n) {
        int o = g_off[i] + g_bsum[blockIdx.x];
        g_off[i] = o;
        g_cur[i] = o;
    }
}

// ---------------- K5: scatter edge data into CSR order ------------------------
// Writes (r,t) pair and precomputed sr[r]+st[t] so k_fused needs NO gathers
// for the score pass.
__global__ void k_scatter(const int* __restrict__ h_index, const int* __restrict__ r_index,
                          const int* __restrict__ t_index, int e) {
    int i = blockIdx.x * blockDim.x + threadIdx.x;
    if (i < e) {
        int rr = r_index[i];
        int tt = t_index[i];
        int p = atomicAdd(&g_cur[h_index[i]], 1);
        g_rt[p] = make_int2(rr, tt);
        g_srt[p] = g_sr[rr] + g_st[tt];
    }
}

// ---------------- K6: fused segment softmax + reduce + bias + relu ------------
// One warp per destination. Pass A: lane-parallel max over contiguous scores.
// Pass B: per-lane weights (contiguous), shfl-broadcast (w, rr, tt), all lanes
// gather RE/TE float4s — every load independent, high MLP.
__global__ void k_fused(const float* __restrict__ a_b, const float* __restrict__ bias,
                        float* __restrict__ out, int ne)
{
    int w = (blockIdx.x * blockDim.x + threadIdx.x) >> 5;
    int lane = threadIdx.x & 31;
    if (w >= ne) return;
    int o0 = g_off[w];
    int deg = g_off[w + 1] - o0;
    float4 b4 = *(const float4*)&bias[lane * 4];
    float4 res;
    if (deg == 0) {
        res.x = fmaxf(b4.x, 0.f); res.y = fmaxf(b4.y, 0.f);
        res.z = fmaxf(b4.z, 0.f); res.w = fmaxf(b4.w, 0.f);
    } else {
        float sb = g_sh[w] + a_b[0];
        // pass A: segment max (contiguous loads, lane-strided)
        float m = -INFINITY;
        for (int i = lane; i < deg; i += 32) {
            float s = sb + g_srt[o0 + i];
            s = (s >= 0.f) ? s : 0.2f * s;
            s = (s >= 0.f) ? s : 0.2f * s;
            m = fmaxf(m, s);
        }
#pragma unroll
        for (int d = 16; d; d >>= 1) m = fmaxf(m, __shfl_xor_sync(0xFFFFFFFFu, m, d));
        // pass B: chunks of 32 edges
        float denom = 0.f;
        float4 acc = make_float4(0.f, 0.f, 0.f, 0.f);
        for (int base = 0; base < deg; base += 32) {
            int n = min(32, deg - base);
            float wgt = 0.f;
            int2 my = make_int2(0, 0);
            if (lane < n) {
                float s = sb + g_srt[o0 + base + lane];
                s = (s >= 0.f) ? s : 0.2f * s;
                s = (s >= 0.f) ? s : 0.2f * s;
                wgt = __expf(s - m);
                my = g_rt[o0 + base + lane];
            }
            denom += wgt;
            for (int j = 0; j < n; j++) {
                float wg = __shfl_sync(0xFFFFFFFFu, wgt, j);
                int rr = __shfl_sync(0xFFFFFFFFu, my.x, j);
                int tt = __shfl_sync(0xFFFFFFFFu, my.y, j);
                float4 fr = *(const float4*)&g_RE[rr * 256 + lane * 4];
                float4 ft = *(const float4*)&g_HT[tt * 256 + 128 + lane * 4];
                acc.x += wg * (fr.x + ft.x);
                acc.y += wg * (fr.y + ft.y);
                acc.z += wg * (fr.z + ft.z);
                acc.w += wg * (fr.w + ft.w);
            }
        }
#pragma unroll
        for (int d = 16; d; d >>= 1) denom += __shfl_xor_sync(0xFFFFFFFFu, denom, d);
        float inv = 1.f / denom;
        float4 he = *(const float4*)&g_HT[w * 256 + lane * 4];
        res.x = fmaxf(he.x + acc.x * inv + b4.x, 0.f);
        res.y = fmaxf(he.y + acc.y * inv + b4.y, 0.f);
        res.z = fmaxf(he.z + acc.z * inv + b4.z, 0.f);
        res.w = fmaxf(he.w + acc.w * inv + b4.w, 0.f);
    }
    *(float4*)&out[w * 128 + lane * 4] = res;
}

// ---------------- host ---------------------------------------------------------
extern "C" void kernel_launch(void* const* d_in, const int* in_sizes, int n_in,
                              void* d_out, int out_size)
{
    const int*   h_index = (const int*)d_in[0];
    const int*   r_index = (const int*)d_in[1];
    const int*   t_index = (const int*)d_in[2];
    const float* ent     = (const float*)d_in[3];
    const float* rel     = (const float*)d_in[4];
    const float* W       = (const float*)d_in[5];
    const float* a       = (const float*)d_in[6];
    const float* a_b     = (const float*)d_in[7];
    const float* bias    = (const float*)d_in[8];
    float* out = (float*)d_out;

    const int E  = in_sizes[0];
    const int NE = in_sizes[3] / 128;
    const int NR = in_sizes[4] / 128;

    float* p_HT; cudaGetSymbolAddress((void**)&p_HT, g_HT);
    float* p_RE; cudaGetSymbolAddress((void**)&p_RE, g_RE);
    float* p_sh; cudaGetSymbolAddress((void**)&p_sh, g_sh);
    float* p_st; cudaGetSymbolAddress((void**)&p_st, g_st);
    float* p_sr; cudaGetSymbolAddress((void**)&p_sr, g_sr);

    cudaFuncSetAttribute(k_gemm_tc, cudaFuncAttributeMaxDynamicSharedMemorySize,
                         GEMM_SMEM_BYTES);

    const int nb = (NE + 1023) / 1024;     // scan blocks (<=128 for NE<=131072)

    // init degree histogram
    k_init<<<nb, 1024>>>(NE);
    // HT = Ent @ [W_h | W_t] with fused sh/st dots (tensor cores, tf32)
    {
        dim3 grid((NE + 63) / 64, 2);
        k_gemm_tc<<<grid, 128, GEMM_SMEM_BYTES>>>(ent, NE, W, 0, 256, p_HT, p_sh, p_st, a);
    }
    // RE = Rel @ W_r with fused sr dot
    {
        dim3 grid((NR + 63) / 64, 1);
        k_gemm_tc<<<grid, 128, GEMM_SMEM_BYTES>>>(rel, NR, W, 128, 128, p_RE, p_sr, p_sr, a);
    }
    // CSR build by destination (h_index)
    k_hist<<<(E + 1023) / 1024, 1024>>>(h_index, E);
    k_scan_blk<<<nb, 1024>>>(NE);
    k_scan_top<<<1, 128>>>(nb, E, NE);
    k_scan_add<<<nb, 1024>>>(NE);
    k_scatter<<<(E + 1023) / 1024, 1024>>>(h_index, r_index, t_index, E);
    // fused softmax + message reduce + bias + relu
    k_fused<<<(NE * 32 + 255) / 256, 256>>>(a_b, bias, out, NE);
}

// round 7
// speedup vs baseline: 2.4416x; 1.2259x over previous
#include <cuda_runtime.h>
#include <cuda_fp16.h>
#include <math.h>
#include <stdint.h>

// Problem shape (fixed by the dataset)
#define NE_MAX 100000
#define NR_MAX 1000
#define E_MAX  500000

// ---------------- scratch (device globals: no allocation allowed) -------------
__device__ float  g_HE[NE_MAX * 128];    // Ent@W_h (fp32, exact path)
__device__ __half g_TEh[NE_MAX * 128];   // Ent@W_t (fp16 message table)
__device__ __half g_REh[NR_MAX * 128];   // Rel@W_r (fp16 message table)
__device__ float  g_sh[NE_MAX];
__device__ float  g_st[NE_MAX];
__device__ float  g_sr[NR_MAX];
__device__ int    g_deg[NE_MAX];
__device__ int    g_off[NE_MAX + 1];
__device__ int    g_cur[NE_MAX];
__device__ unsigned int g_smax[NE_MAX];  // order-encoded float segment max
__device__ int    g_bsum[128];
__device__ uint2  g_es[E_MAX];           // CSR-ordered (score bits, rr<<17|tt)

// ---------------- helpers ------------------------------------------------------
__device__ __forceinline__ uint32_t f2tf32(float x) {
    uint32_t r;
    asm("cvt.rna.tf32.f32 %0, %1;" : "=r"(r) : "f"(x));
    return r;
}

__device__ __forceinline__ unsigned int fkey(float f) {
    unsigned int u = __float_as_uint(f);
    return (u & 0x80000000u) ? ~u : (u | 0x80000000u);
}
__device__ __forceinline__ float funkey(unsigned int k) {
    return __uint_as_float((k & 0x80000000u) ? (k ^ 0x80000000u) : ~k);
}

__device__ __forceinline__ void mma_tf32(float4& c,
                                         uint32_t a0, uint32_t a1, uint32_t a2, uint32_t a3,
                                         uint32_t b0, uint32_t b1) {
    asm volatile(
        "mma.sync.aligned.m16n8k8.row.col.f32.tf32.tf32.f32 "
        "{%0,%1,%2,%3}, {%4,%5,%6,%7}, {%8,%9}, {%0,%1,%2,%3};\n"
        : "+f"(c.x), "+f"(c.y), "+f"(c.z), "+f"(c.w)
        : "r"(a0), "r"(a1), "r"(a2), "r"(a3), "r"(b0), "r"(b1));
}

// ---------------- K0: init ----------------------------------------------------
__global__ void k_init(int ne) {
    int i = blockIdx.x * blockDim.x + threadIdx.x;
    if (i < ne) { g_deg[i] = 0; g_smax[i] = 0u; }
}

// ---------------- K1: tensor-core GEMM + fused attention dot -------------------
// Permuted smem layouts for vectorized operand LDS:
//  As2[row][p], p = ks*8 + tig*2 + b  (b: k-halves 0/4)   -> LDS.64 per (row,ks)
//  Ws2[k][gid*16 + j]                                     -> LDS.128 per (k,gid,jquad)
#define A_PAD2 136   // mod 32 == 8 -> 2-phase A loads
#define W_PAD2 132   // mod 32 == 4 -> 4-phase B loads (minimum)
#define GEMM_SMEM_BYTES ((64 * A_PAD2 + 128 * W_PAD2 + 128) * 4)

__global__ __launch_bounds__(128) void k_gemm_tc(
    const float* __restrict__ A, int n_rows,
    const float* __restrict__ W, int woff0, int woff1,
    float* __restrict__ Cf,        // fp32 out (yy==0 when half_yy0==0)
    __half* __restrict__ Ch,       // fp16 out
    int half_yy0,
    float* __restrict__ dot0, float* __restrict__ dot1,
    const float* __restrict__ a_vec)
{
    extern __shared__ uint32_t smem[];
    uint32_t* As2 = smem;                        // [64][A_PAD2]
    uint32_t* Ws2 = As2 + 64 * A_PAD2;           // [128][W_PAD2]
    float*    a_s = (float*)(Ws2 + 128 * W_PAD2);

    const int t    = threadIdx.x;
    const int warp = t >> 5;
    const int lane = t & 31;
    const int gid  = lane >> 2;
    const int tig  = lane & 3;
    const int row0 = blockIdx.x * 64;
    const int yy   = blockIdx.y;
    const int woff = yy == 0 ? woff0 : woff1;
    const bool use_half = (yy == 1) || half_yy0;
    float* dotp = yy == 0 ? dot0 : dot1;

    // stage A tile (64 x 128) into permuted layout
#pragma unroll
    for (int i = 0; i < 16; i++) {
        int idx = t + i * 128;
        int r   = idx >> 5;
        int c4  = (idx & 31) * 4;
        float4 v = make_float4(0.f, 0.f, 0.f, 0.f);
        int gr = row0 + r;
        if (gr < n_rows) v = *(const float4*)&A[gr * 128 + c4];
        uint32_t* dst = &As2[r * A_PAD2];
        int k = c4;
        int p = ((k >> 3) << 3) + ((k & 3) << 1) + ((k >> 2) & 1);
        // successive k within the float4 advance (k&3) -> p stride 2
        dst[p]     = f2tf32(v.x);
        dst[p + 2] = f2tf32(v.y);
        dst[p + 4] = f2tf32(v.z);
        dst[p + 6] = f2tf32(v.w);
    }
    // stage W tile (128 x 128) into permuted layout
#pragma unroll
    for (int i = 0; i < 32; i++) {
        int idx = t + i * 128;
        int r   = idx >> 5;
        int c4  = (idx & 31) * 4;
        float4 v = *(const float4*)&W[(woff + r) * 128 + c4];
        uint32_t* dst = &Ws2[r * W_PAD2];
        int p0 = ((c4 & 7) << 4) + (c4 >> 3);
        int p1 = (((c4 + 1) & 7) << 4) + ((c4 + 1) >> 3);
        int p2 = (((c4 + 2) & 7) << 4) + ((c4 + 2) >> 3);
        int p3 = (((c4 + 3) & 7) << 4) + ((c4 + 3) >> 3);
        dst[p0] = f2tf32(v.x); dst[p1] = f2tf32(v.y);
        dst[p2] = f2tf32(v.z); dst[p3] = f2tf32(v.w);
    }
    if (t < 128) a_s[t] = a_vec[t];
    __syncthreads();

    float4 cacc[16];
#pragma unroll
    for (int j = 0; j < 16; j++) cacc[j] = make_float4(0.f, 0.f, 0.f, 0.f);

    const int ra = 16 * warp + gid;
    const uint32_t* Ar1 = &As2[ra * A_PAD2 + tig * 2];
    const uint32_t* Ar2 = &As2[(ra + 8) * A_PAD2 + tig * 2];
#pragma unroll
    for (int ks = 0; ks < 16; ks++) {
        uint2 av1 = *(const uint2*)&Ar1[ks * 8];      // (a0, a2): row ra,  k = tig, tig+4
        uint2 av2 = *(const uint2*)&Ar2[ks * 8];      // (a1, a3): row ra+8
        const uint32_t* Br0 = &Ws2[(ks * 8 + tig) * W_PAD2 + gid * 16];
        const uint32_t* Br1 = &Ws2[(ks * 8 + tig + 4) * W_PAD2 + gid * 16];
#pragma unroll
        for (int c = 0; c < 4; c++) {
            uint4 b0 = *(const uint4*)&Br0[c * 4];
            uint4 b1 = *(const uint4*)&Br1[c * 4];
            mma_tf32(cacc[4 * c + 0], av1.x, av2.x, av1.y, av2.y, b0.x, b1.x);
            mma_tf32(cacc[4 * c + 1], av1.x, av2.x, av1.y, av2.y, b0.y, b1.y);
            mma_tf32(cacc[4 * c + 2], av1.x, av2.x, av1.y, av2.y, b0.z, b1.z);
            mma_tf32(cacc[4 * c + 3], av1.x, av2.x, av1.y, av2.y, b0.w, b1.w);
        }
    }

    // epilogue: store C (fp32 or fp16) and fused dot with a
    const int rg1 = row0 + 16 * warp + gid;
    const int rg2 = rg1 + 8;
    const bool v1 = rg1 < n_rows;
    const bool v2 = rg2 < n_rows;
    float p1 = 0.f, p2 = 0.f;
#pragma unroll
    for (int j = 0; j < 16; j++) {
        int cl = j * 8 + 2 * tig;
        float ax = a_s[cl], ay = a_s[cl + 1];
        p1 += cacc[j].x * ax + cacc[j].y * ay;
        p2 += cacc[j].z * ax + cacc[j].w * ay;
        if (use_half) {
            if (v1) *(__half2*)&Ch[rg1 * 128 + cl] = __floats2half2_rn(cacc[j].x, cacc[j].y);
            if (v2) *(__half2*)&Ch[rg2 * 128 + cl] = __floats2half2_rn(cacc[j].z, cacc[j].w);
        } else {
            if (v1) *(float2*)&Cf[rg1 * 128 + cl] = make_float2(cacc[j].x, cacc[j].y);
            if (v2) *(float2*)&Cf[rg2 * 128 + cl] = make_float2(cacc[j].z, cacc[j].w);
        }
    }
    p1 += __shfl_xor_sync(0xFFFFFFFFu, p1, 1);
    p1 += __shfl_xor_sync(0xFFFFFFFFu, p1, 2);
    p2 += __shfl_xor_sync(0xFFFFFFFFu, p2, 1);
    p2 += __shfl_xor_sync(0xFFFFFFFFu, p2, 2);
    if (tig == 0) {
        if (v1) dotp[rg1] = p1;
        if (v2) dotp[rg2] = p2;
    }
}

// ---------------- K3: histogram of destination degrees ------------------------
__global__ void k_hist(const int* __restrict__ h_index, int e) {
    int i = blockIdx.x * blockDim.x + threadIdx.x;
    if (i < e) atomicAdd(&g_deg[h_index[i]], 1);
}

// ---------------- K4a: per-block exclusive scan + block sums -------------------
__global__ __launch_bounds__(1024) void k_scan_blk(int n) {
    __shared__ int warp_tot[32];
    const int t = threadIdx.x;
    const int lane = t & 31;
    const int wid = t >> 5;
    int i = blockIdx.x * 1024 + t;
    int v = (i < n) ? g_deg[i] : 0;
    int s = v;
#pragma unroll
    for (int d = 1; d < 32; d <<= 1) {
        int x = __shfl_up_sync(0xFFFFFFFFu, s, d);
        if (lane >= d) s += x;
    }
    if (lane == 31) warp_tot[wid] = s;
    __syncthreads();
    if (wid == 0) {
        int wv = warp_tot[lane];
        int ws = wv;
#pragma unroll
        for (int d = 1; d < 32; d <<= 1) {
            int x = __shfl_up_sync(0xFFFFFFFFu, ws, d);
            if (lane >= d) ws += x;
        }
        warp_tot[lane] = ws - wv;
    }
    __syncthreads();
    int excl = warp_tot[wid] + s - v;
    if (i < n) g_off[i] = excl;            // block-local exclusive
    if (t == 1023) g_bsum[blockIdx.x] = excl + v;
}

// ---------------- K4b: top-level scan of block sums (nb <= 128) ---------------
__global__ __launch_bounds__(128) void k_scan_top(int nb, int etot, int n) {
    __shared__ int wt[4];
    const int t = threadIdx.x;
    const int lane = t & 31;
    const int wid = t >> 5;
    int v = (t < nb) ? g_bsum[t] : 0;
    int s = v;
#pragma unroll
    for (int d = 1; d < 32; d <<= 1) {
        int x = __shfl_up_sync(0xFFFFFFFFu, s, d);
        if (lane >= d) s += x;
    }
    if (lane == 31) wt[wid] = s;
    __syncthreads();
    int off = 0;
#pragma unroll
    for (int k = 0; k < 4; k++) if (k < wid) off += wt[k];
    g_bsum[t] = off + s - v;               // exclusive
    if (t == 0) g_off[n] = etot;
}

// ---------------- K4c: add block offsets, init cursors ------------------------
__global__ __launch_bounds__(1024) void k_scan_add(int n) {
    int i = blockIdx.x * 1024 + threadIdx.x;
    if (i < n) {
        int o = g_off[i] + g_bsum[blockIdx.x];
        g_off[i] = o;
        g_cur[i] = o;
    }
}

// ---------------- K5: scatter edge records + segment max ----------------------
// Computes the full leaky^2 score per edge, writes packed (score, rr|tt) in CSR
// order, and maintains the per-segment running max via encoded atomicMax.
__global__ void k_scatter(const int* __restrict__ h_index, const int* __restrict__ r_index,
                          const int* __restrict__ t_index, const float* __restrict__ a_b,
                          int e) {
    int i = blockIdx.x * blockDim.x + threadIdx.x;
    if (i < e) {
        int hh = h_index[i];
        int rr = r_index[i];
        int tt = t_index[i];
        float s = (g_sh[hh] + a_b[0]) + (g_sr[rr] + g_st[tt]);
        s = (s >= 0.f) ? s : 0.2f * s;     // inner leaky
        s = (s >= 0.f) ? s : 0.2f * s;     // outer leaky
        int p = atomicAdd(&g_cur[hh], 1);
        g_es[p] = make_uint2(__float_as_uint(s), ((unsigned)rr << 17) | (unsigned)tt);
        atomicMax(&g_smax[hh], fkey(s));
    }
}

// ---------------- K6: fused segment softmax + reduce + bias + relu ------------
// One warp per destination; single pass (max precomputed by scatter).
__global__ void k_fused(const float* __restrict__ bias,
                        float* __restrict__ out, int ne)
{
    int w = (blockIdx.x * blockDim.x + threadIdx.x) >> 5;
    int lane = threadIdx.x & 31;
    if (w >= ne) return;
    int o0 = g_off[w];
    int deg = g_off[w + 1] - o0;
    float4 b4 = *(const float4*)&bias[lane * 4];
    float4 res;
    if (deg == 0) {
        res.x = fmaxf(b4.x, 0.f); res.y = fmaxf(b4.y, 0.f);
        res.z = fmaxf(b4.z, 0.f); res.w = fmaxf(b4.w, 0.f);
    } else {
        float m = funkey(g_smax[w]);
        float denom = 0.f;
        float4 acc = make_float4(0.f, 0.f, 0.f, 0.f);
        for (int base = 0; base < deg; base += 32) {
            int n = min(32, deg - base);
            float wgt = 0.f;
            unsigned pk = 0;
            if (lane < n) {
                uint2 er = g_es[o0 + base + lane];
                wgt = __expf(__uint_as_float(er.x) - m);
                pk = er.y;
            }
            denom += wgt;
            for (int j = 0; j < n; j++) {
                float wg = __shfl_sync(0xFFFFFFFFu, wgt, j);
                unsigned pj = __shfl_sync(0xFFFFFFFFu, pk, j);
                int rr = pj >> 17;
                int tt = pj & 0x1FFFF;
                // 4 halfs per lane from each table (8B loads)
                __half2 fr0 = *(const __half2*)&g_REh[rr * 128 + lane * 4];
                __half2 fr1 = *(const __half2*)&g_REh[rr * 128 + lane * 4 + 2];
                __half2 ft0 = *(const __half2*)&g_TEh[tt * 128 + lane * 4];
                __half2 ft1 = *(const __half2*)&g_TEh[tt * 128 + lane * 4 + 2];
                float2 a0 = __half22float2(fr0), a1 = __half22float2(fr1);
                float2 c0 = __half22float2(ft0), c1 = __half22float2(ft1);
                acc.x += wg * (a0.x + c0.x);
                acc.y += wg * (a0.y + c0.y);
                acc.z += wg * (a1.x + c1.x);
                acc.w += wg * (a1.y + c1.y);
            }
        }
#pragma unroll
        for (int d = 16; d; d >>= 1) denom += __shfl_xor_sync(0xFFFFFFFFu, denom, d);
        float inv = 1.f / denom;
        float4 he = *(const float4*)&g_HE[w * 128 + lane * 4];
        res.x = fmaxf(he.x + acc.x * inv + b4.x, 0.f);
        res.y = fmaxf(he.y + acc.y * inv + b4.y, 0.f);
        res.z = fmaxf(he.z + acc.z * inv + b4.z, 0.f);
        res.w = fmaxf(he.w + acc.w * inv + b4.w, 0.f);
    }
    *(float4*)&out[w * 128 + lane * 4] = res;
}

// ---------------- host ---------------------------------------------------------
extern "C" void kernel_launch(void* const* d_in, const int* in_sizes, int n_in,
                              void* d_out, int out_size)
{
    const int*   h_index = (const int*)d_in[0];
    const int*   r_index = (const int*)d_in[1];
    const int*   t_index = (const int*)d_in[2];
    const float* ent     = (const float*)d_in[3];
    const float* rel     = (const float*)d_in[4];
    const float* W       = (const float*)d_in[5];
    const float* a       = (const float*)d_in[6];
    const float* a_b     = (const float*)d_in[7];
    const float* bias    = (const float*)d_in[8];
    float* out = (float*)d_out;

    const int E  = in_sizes[0];
    const int NE = in_sizes[3] / 128;
    const int NR = in_sizes[4] / 128;

    float*  p_HE;  cudaGetSymbolAddress((void**)&p_HE,  g_HE);
    __half* p_TEh; cudaGetSymbolAddress((void**)&p_TEh, g_TEh);
    __half* p_REh; cudaGetSymbolAddress((void**)&p_REh, g_REh);
    float*  p_sh;  cudaGetSymbolAddress((void**)&p_sh,  g_sh);
    float*  p_st;  cudaGetSymbolAddress((void**)&p_st,  g_st);
    float*  p_sr;  cudaGetSymbolAddress((void**)&p_sr,  g_sr);

    cudaFuncSetAttribute(k_gemm_tc, cudaFuncAttributeMaxDynamicSharedMemorySize,
                         GEMM_SMEM_BYTES);

    const int nb = (NE + 1023) / 1024;     // scan blocks (<=128 for NE<=131072)

    // init degree histogram + segment max
    k_init<<<nb, 1024>>>(NE);
    // HE (fp32) / TE (fp16) = Ent @ [W_h | W_t], fused sh/st dots
    {
        dim3 grid((NE + 63) / 64, 2);
        k_gemm_tc<<<grid, 128, GEMM_SMEM_BYTES>>>(ent, NE, W, 0, 256,
                                                  p_HE, p_TEh, 0, p_sh, p_st, a);
    }
    // RE (fp16) = Rel @ W_r, fused sr dot
    {
        dim3 grid((NR + 63) / 64, 1);
        k_gemm_tc<<<grid, 128, GEMM_SMEM_BYTES>>>(rel, NR, W, 128, 128,
                                                  (float*)0, p_REh, 1, p_sr, p_sr, a);
    }
    // CSR build by destination (h_index)
    k_hist<<<(E + 1023) / 1024, 1024>>>(h_index, E);
    k_scan_blk<<<nb, 1024>>>(NE);
    k_scan_top<<<1, 128>>>(nb, E, NE);
    k_scan_add<<<nb, 1024>>>(NE);
    // scatter packed edge records + per-segment max
    k_scatter<<<(E + 1023) / 1024, 1024>>>(h_index, r_index, t_index, a_b, E);
    // fused softmax + message reduce + bias + relu (single pass)
    k_fused<<<(NE * 32 + 255) / 256, 256>>>(bias, out, NE);
}